// round 14
// baseline (speedup 1.0000x reference)
#include <cuda_runtime.h>
#include <cuda_fp16.h>
#include <math.h>
#include <stdint.h>

#define T_TOK 4096
#define H_DIM 1024
#define FF_DIM 2048
#define NEXP 8
#define SSH 72           // padded row stride in halves (144 B)
#define STAGES 3
#define WBLK 16384       // w1/w3-conversion blocks in prolog
#define G1T  8192        // gemm1 GEMM tiles (32 ff x 32 row x 8 e)
#define W2BLK 8192       // w2-conversion blocks appended to gemm1 grid

// ---------------- device scratch (allocation-guard safe) --------------------
__device__ int      g_counts[NEXP];              // zero-init; combine re-zeros
__device__ int      g_tok[NEXP][T_TOK];          // packed: tok | slot<<16
__device__ float    g_wslot[2 * T_TOK];
__device__ __half   g_innerh[(size_t)NEXP * T_TOK * FF_DIM];  // 128 MB
__device__ __half   g_combh[(size_t)2 * T_TOK * H_DIM];       // 16 MB (weighted)
__device__ __half   g_w1h[(size_t)NEXP * FF_DIM * H_DIM];     // 32 MB
__device__ __half   g_w3h[(size_t)NEXP * FF_DIM * H_DIM];     // 32 MB
__device__ __half   g_w2h[(size_t)NEXP * H_DIM * FF_DIM];     // 32 MB
__device__ __half   g_xh[(size_t)T_TOK * H_DIM];              // 8 MB

// ---------------- helpers ----------------------------------------------------
__device__ __forceinline__ uint32_t h2u(float a, float b) {
    __half2 h = __floats2half2_rn(a, b);
    return *(uint32_t*)&h;
}
__device__ __forceinline__ uint2 cvt4h(float4 v) {
    uint2 u; u.x = h2u(v.x, v.y); u.y = h2u(v.z, v.w); return u;
}
__device__ __forceinline__ void mma16h(float* c, const uint32_t* a, const uint32_t* b) {
    asm volatile(
        "mma.sync.aligned.m16n8k16.row.col.f32.f16.f16.f32 "
        "{%0,%1,%2,%3}, {%4,%5,%6,%7}, {%8,%9}, {%0,%1,%2,%3};"
        : "+f"(c[0]), "+f"(c[1]), "+f"(c[2]), "+f"(c[3])
        : "r"(a[0]), "r"(a[1]), "r"(a[2]), "r"(a[3]), "r"(b[0]), "r"(b[1]));
}
#define LDSM4(r0, r1, r2, r3, addr) \
    asm volatile("ldmatrix.sync.aligned.m8n8.x4.shared.b16 {%0,%1,%2,%3}, [%4];" \
                 : "=r"(r0), "=r"(r1), "=r"(r2), "=r"(r3) : "r"(addr))
#define CP16(dst, src) \
    asm volatile("cp.async.cg.shared.global [%0], [%1], 16;" \
                 :: "r"(dst), "l"(src) : "memory")
#define CPCOMMIT() asm volatile("cp.async.commit_group;" ::: "memory")
#define CPWAIT1()  asm volatile("cp.async.wait_group 1;" ::: "memory")
#define CPWAIT0()  asm volatile("cp.async.wait_group 0;" ::: "memory")

// ---------------- prolog: w1/w3 cvt (blocks < WBLK) + router (rest) ---------
// g_counts is re-zeroed by combine_kernel at the end of every invocation
// (and __device__ globals are zero-initialized), so the router always sees
// counts==0 with no intra-kernel race.
__global__ void prolog_kernel(const float* __restrict__ w1,
                              const float* __restrict__ w3,
                              const float* __restrict__ x,
                              const float* __restrict__ gw,
                              float* __restrict__ logits_out,
                              int write_logits) {
    if (blockIdx.x < WBLK) {
        size_t i = (size_t)blockIdx.x * blockDim.x + threadIdx.x;
        ((uint2*)g_w1h)[i] = cvt4h(((const float4*)w1)[i]);
        ((uint2*)g_w3h)[i] = cvt4h(((const float4*)w3)[i]);
        return;
    }

    int warp = (((int)blockIdx.x - WBLK) * blockDim.x + threadIdx.x) >> 5;
    int lane = threadIdx.x & 31;
    if (warp >= T_TOK) return;

    const float* xr = x + (size_t)warp * H_DIM;

    for (int i = lane; i < H_DIM / 2; i += 32) {
        float2 v = ((const float2*)xr)[i];
        ((uint32_t*)g_xh)[(size_t)warp * (H_DIM / 2) + i] = h2u(v.x, v.y);
    }

    float xv[32];
#pragma unroll
    for (int i = 0; i < 32; i++) xv[i] = xr[lane + 32 * i];

    float lg[NEXP];
#pragma unroll
    for (int e = 0; e < NEXP; e++) {
        const float* g = gw + (size_t)e * H_DIM;
        float s = 0.f;
#pragma unroll
        for (int i = 0; i < 32; i++) s += xv[i] * g[lane + 32 * i];
#pragma unroll
        for (int o = 16; o > 0; o >>= 1) s += __shfl_xor_sync(0xffffffffu, s, o);
        lg[e] = s;
    }

    if (lane == 0) {
        if (write_logits) {
#pragma unroll
            for (int e = 0; e < NEXP; e++)
                logits_out[(size_t)warp * NEXP + e] = lg[e];
        }
        float mx = lg[0];
#pragma unroll
        for (int e = 1; e < NEXP; e++) mx = fmaxf(mx, lg[e]);
        float p[NEXP], sum = 0.f;
#pragma unroll
        for (int e = 0; e < NEXP; e++) { p[e] = expf(lg[e] - mx); sum += p[e]; }
#pragma unroll
        for (int e = 0; e < NEXP; e++) p[e] /= sum;
        int i1 = 0;
#pragma unroll
        for (int e = 1; e < NEXP; e++) if (p[e] > p[i1]) i1 = e;
        int i2 = (i1 == 0) ? 1 : 0;
#pragma unroll
        for (int e = 0; e < NEXP; e++) if (e != i1 && p[e] > p[i2]) i2 = e;
        float s2 = p[i1] + p[i2];
        int pos = atomicAdd(&g_counts[i1], 1);
        g_tok[i1][pos] = warp;                 // slot 0
        pos = atomicAdd(&g_counts[i2], 1);
        g_tok[i2][pos] = warp | 0x10000;       // slot 1
        g_wslot[warp]         = p[i1] / s2;
        g_wslot[T_TOK + warp] = p[i2] / s2;
    }
}

// ---------------- GEMM1 (+ appended w2 conversion blocks) -------------------
// GEMM: block 128M x 32N-dual(64 eff) x 64K; 4 warps = 2M x 2N; warp tile
// 64x32 per matrix; 128 threads, 2 CTAs/SM, 3-stage cp.async ring (frozen).
#define G1_SZ   36864u           // (128+64+64)*144
#define G1_B1O  18432u           // 128*144
#define G1_B3O  27648u           // 192*144

__global__ void __launch_bounds__(128, 2)
gemm1_tc(const float* __restrict__ w2src) {
    extern __shared__ __align__(16) char smc[];
    const uint32_t sbase = (uint32_t)__cvta_generic_to_shared(smc);

    if (blockIdx.x >= G1T) {
        // w2 conversion: 8192 blocks x 128 thr x 4 float4
        size_t i = (size_t)(blockIdx.x - G1T) * 128 + threadIdx.x;
        const float4* src = (const float4*)w2src;
#pragma unroll
        for (int j = 0; j < 4; j++) {
            size_t idx = i + (size_t)j * (W2BLK * 128);
            ((uint2*)g_w2h)[idx] = cvt4h(src[idx]);
        }
        return;
    }

    const int f = blockIdx.x;
    const int e = f >> 10;              // 1024 tiles per expert
    const int row0 = ((f >> 5) & 31) * 128;
    const int ff0 = (f & 31) * 64;
    const int n = g_counts[e];
    if (row0 >= n) return;

    const int tid = threadIdx.x;
    const int wid = tid >> 5, lane = tid & 31;
    const int wm = wid & 1, wn = wid >> 1;        // 2M x 2N
    const int g = lane >> 2, t = lane & 3;

    const __half* apt[8];
#pragma unroll
    for (int i = 0; i < 8; i++) {
        int r = row0 + (tid >> 3) + 16 * i;
        int tok = (r < n) ? (g_tok[e][r] & 0xFFFF) : 0;
        apt[i] = g_xh + (size_t)tok * H_DIM + (tid & 7) * 8;
    }
    const __half* b1p0 = g_w1h + ((size_t)e * FF_DIM + ff0 + (tid >> 3)) * H_DIM + (tid & 7) * 8;
    const __half* b3p0 = g_w3h + ((size_t)e * FF_DIM + ff0 + (tid >> 3)) * H_DIM + (tid & 7) * 8;
    const uint32_t off0 = (uint32_t)((tid >> 3) * SSH + (tid & 7) * 8) * 2u;
    const uint32_t ostep = 16u * SSH * 2u;

    auto issue = [&](int s) {
        uint32_t base = sbase + (uint32_t)(s % STAGES) * G1_SZ;
        int k0 = s * 64;
        uint32_t o = off0;
#pragma unroll
        for (int i = 0; i < 8; i++) { CP16(base + o, apt[i] + k0); o += ostep; }
        o = off0;
#pragma unroll
        for (int i = 0; i < 4; i++) {
            CP16(base + G1_B1O + o, b1p0 + (size_t)16 * i * H_DIM + k0);
            CP16(base + G1_B3O + o, b3p0 + (size_t)16 * i * H_DIM + k0);
            o += ostep;
        }
        CPCOMMIT();
    };

    float acc1[4][4][4], acc3[4][4][4];
#pragma unroll
    for (int mb = 0; mb < 4; mb++)
#pragma unroll
        for (int nb = 0; nb < 4; nb++)
#pragma unroll
            for (int j = 0; j < 4; j++) { acc1[mb][nb][j] = 0.f; acc3[mb][nb][j] = 0.f; }

    uint32_t aLb0 = (uint32_t)((wm * 64 + (lane & 15)) * SSH) * 2u
                  + (uint32_t)(lane >> 4) * 16u;
    const uint32_t aMstep = 16u * SSH * 2u;
    uint32_t bLb[2];
#pragma unroll
    for (int p = 0; p < 2; p++)
        bLb[p] = (uint32_t)((wn * 32 + p * 16 + ((lane >> 4) << 3) + (lane & 7)) * SSH) * 2u
               + (uint32_t)((lane >> 3) & 1) * 16u;

    issue(0); issue(1);

    const int NIT = H_DIM / 64;     // 16
    for (int it = 0; it < NIT; ++it) {
        if (it + 1 < NIT) CPWAIT1(); else CPWAIT0();
        __syncthreads();
        if (it + STAGES - 1 < NIT) issue(it + STAGES - 1);

        const uint32_t sb  = sbase + (uint32_t)(it % STAGES) * G1_SZ;
        const uint32_t b1b = sb + G1_B1O;
        const uint32_t b3b = sb + G1_B3O;

#pragma unroll
        for (int kk = 0; kk < 4; kk++) {
            const uint32_t ko = (uint32_t)kk * 32u;
            uint32_t a[4][4], b1[4][2], b3[4][2];
#pragma unroll
            for (int mb = 0; mb < 4; mb++)
                LDSM4(a[mb][0], a[mb][1], a[mb][2], a[mb][3],
                      sb + aLb0 + (uint32_t)mb * aMstep + ko);
#pragma unroll
            for (int p = 0; p < 2; p++) {
                LDSM4(b1[2*p][0], b1[2*p][1], b1[2*p+1][0], b1[2*p+1][1], b1b + bLb[p] + ko);
                LDSM4(b3[2*p][0], b3[2*p][1], b3[2*p+1][0], b3[2*p+1][1], b3b + bLb[p] + ko);
            }
#pragma unroll
            for (int mb = 0; mb < 4; mb++)
#pragma unroll
                for (int nb = 0; nb < 4; nb++) {
                    mma16h(acc1[mb][nb], a[mb], b1[nb]);
                    mma16h(acc3[mb][nb], a[mb], b3[nb]);
                }
        }
    }

    // fused SwiGLU epilogue -> g_innerh
#pragma unroll
    for (int mb = 0; mb < 4; mb++) {
        int r0 = row0 + wm * 64 + mb * 16 + g;
        int r1 = r0 + 8;
#pragma unroll
        for (int nb = 0; nb < 4; nb++) {
            int col = ff0 + wn * 32 + nb * 8 + 2 * t;
            if (r0 < n) {
                float a0 = acc1[mb][nb][0], a1 = acc1[mb][nb][1];
                float v0 = (a0 / (1.f + expf(-a0))) * acc3[mb][nb][0];
                float v1 = (a1 / (1.f + expf(-a1))) * acc3[mb][nb][1];
                *(uint32_t*)&g_innerh[((size_t)e * T_TOK + r0) * FF_DIM + col] = h2u(v0, v1);
            }
            if (r1 < n) {
                float a2 = acc1[mb][nb][2], a3 = acc1[mb][nb][3];
                float v2 = (a2 / (1.f + expf(-a2))) * acc3[mb][nb][2];
                float v3 = (a3 / (1.f + expf(-a3))) * acc3[mb][nb][3];
                *(uint32_t*)&g_innerh[((size_t)e * T_TOK + r1) * FF_DIM + col] = h2u(v2, v3);
            }
        }
    }
}

// ---------------- GEMM2: combh[slot][tok] = w * (inner @ W2^T), fp16 out ----
// block 128M x 128N x 64K; 4 warps = 2M x 2N; warp tile 64x64.
// 128 threads, 2 CTAs/SM, 3-stage cp.async ring. (GEMM core frozen)
#define G2_SZ  36864u            // (128+128)*144
#define G2_BO  18432u            // 128*144

__global__ void __launch_bounds__(128, 2)
gemm2_tc(const float* __restrict__ dummy) {
    extern __shared__ __align__(16) char smc[];
    const uint32_t sbase = (uint32_t)__cvta_generic_to_shared(smc);

    const int e = blockIdx.z;
    const int n = g_counts[e];
    const int row0 = blockIdx.y * 128;
    if (row0 >= n) return;
    const int h0 = blockIdx.x * 128;

    const int tid = threadIdx.x;
    const int wid = tid >> 5, lane = tid & 31;
    const int wm = wid & 1, wn = wid >> 1;        // 2M x 2N
    const int g = lane >> 2, t = lane & 3;

    const __half* ap0 = g_innerh + ((size_t)e * T_TOK + row0 + (tid >> 3)) * FF_DIM + (tid & 7) * 8;
    const __half* bp0 = g_w2h + ((size_t)e * H_DIM + h0 + (tid >> 3)) * FF_DIM + (tid & 7) * 8;
    const uint32_t off0 = (uint32_t)((tid >> 3) * SSH + (tid & 7) * 8) * 2u;
    const uint32_t ostep = 16u * SSH * 2u;
    const size_t pstep = (size_t)16 * FF_DIM;

    auto issue = [&](int s) {
        uint32_t base = sbase + (uint32_t)(s % STAGES) * G2_SZ;
        int k0 = s * 64;
        const __half* ap = ap0 + k0;
        const __half* bp = bp0 + k0;
        uint32_t o = off0;
#pragma unroll
        for (int i = 0; i < 8; i++) {
            CP16(base + o, ap);
            CP16(base + G2_BO + o, bp);
            ap += pstep; bp += pstep; o += ostep;
        }
        CPCOMMIT();
    };

    float acc[4][8][4];
#pragma unroll
    for (int mb = 0; mb < 4; mb++)
#pragma unroll
        for (int nb = 0; nb < 8; nb++)
#pragma unroll
            for (int j = 0; j < 4; j++) acc[mb][nb][j] = 0.f;

    uint32_t aLb0 = (uint32_t)((wm * 64 + (lane & 15)) * SSH) * 2u
                  + (uint32_t)(lane >> 4) * 16u;
    const uint32_t aMstep = 16u * SSH * 2u;
    uint32_t bLb[4];
#pragma unroll
    for (int p = 0; p < 4; p++)
        bLb[p] = (uint32_t)((wn * 64 + p * 16 + ((lane >> 4) << 3) + (lane & 7)) * SSH) * 2u
               + (uint32_t)((lane >> 3) & 1) * 16u;

    issue(0); issue(1);

    const int NIT = FF_DIM / 64;    // 32
    for (int it = 0; it < NIT; ++it) {
        if (it + 1 < NIT) CPWAIT1(); else CPWAIT0();
        __syncthreads();
        if (it + STAGES - 1 < NIT) issue(it + STAGES - 1);

        const uint32_t sb = sbase + (uint32_t)(it % STAGES) * G2_SZ;
        const uint32_t bb = sb + G2_BO;

#pragma unroll
        for (int kk = 0; kk < 4; kk++) {
            const uint32_t ko = (uint32_t)kk * 32u;
            uint32_t a[4][4], b[8][2];
#pragma unroll
            for (int mb = 0; mb < 4; mb++)
                LDSM4(a[mb][0], a[mb][1], a[mb][2], a[mb][3],
                      sb + aLb0 + (uint32_t)mb * aMstep + ko);
#pragma unroll
            for (int p = 0; p < 4; p++)
                LDSM4(b[2*p][0], b[2*p][1], b[2*p+1][0], b[2*p+1][1], bb + bLb[p] + ko);
#pragma unroll
            for (int mb = 0; mb < 4; mb++)
#pragma unroll
                for (int nb = 0; nb < 8; nb++)
                    mma16h(acc[mb][nb], a[mb], b[nb]);
        }
    }

    // weighted fp16 scatter into per-slot combine buffers
#pragma unroll
    for (int mb = 0; mb < 4; mb++) {
        int r0 = row0 + wm * 64 + mb * 16 + g;
        int r1 = r0 + 8;
        int pk0 = (r0 < n) ? g_tok[e][r0] : -1;
        int pk1 = (r1 < n) ? g_tok[e][r1] : -1;
        __half* d0 = 0; float wt0 = 0.f;
        __half* d1 = 0; float wt1 = 0.f;
        if (pk0 >= 0) {
            int slot = pk0 >> 16, tok = pk0 & 0xFFFF;
            d0 = &g_combh[((size_t)slot * T_TOK + tok) * H_DIM];
            wt0 = g_wslot[slot * T_TOK + tok];
        }
        if (pk1 >= 0) {
            int slot = pk1 >> 16, tok = pk1 & 0xFFFF;
            d1 = &g_combh[((size_t)slot * T_TOK + tok) * H_DIM];
            wt1 = g_wslot[slot * T_TOK + tok];
        }
#pragma unroll
        for (int nb = 0; nb < 8; nb++) {
            int col = h0 + wn * 64 + nb * 8 + 2 * t;
            if (d0) *(uint32_t*)&d0[col] = h2u(wt0 * acc[mb][nb][0], wt0 * acc[mb][nb][1]);
            if (d1) *(uint32_t*)&d1[col] = h2u(wt1 * acc[mb][nb][2], wt1 * acc[mb][nb][3]);
        }
    }
}

// ---------------- combine: out = combh[0] + combh[1]; re-zero counts --------
__global__ void combine_kernel(float* __restrict__ out) {
    int idx = blockIdx.x * blockDim.x + threadIdx.x;
    const int nq = T_TOK * H_DIM / 8;        // uint4 = 8 halves
    if (blockIdx.x == 0 && threadIdx.x < NEXP)
        g_counts[threadIdx.x] = 0;           // reset for the NEXT invocation
    if (idx >= nq) return;
    uint4 u0 = ((const uint4*)g_combh)[idx];
    uint4 u1 = ((const uint4*)g_combh)[(size_t)nq + idx];
    const __half2* h0 = (const __half2*)&u0;
    const __half2* h1 = (const __half2*)&u1;
    float4 r0, r1;
    {
        float2 a = __half22float2(h0[0]), b = __half22float2(h1[0]);
        r0.x = a.x + b.x; r0.y = a.y + b.y;
        a = __half22float2(h0[1]); b = __half22float2(h1[1]);
        r0.z = a.x + b.x; r0.w = a.y + b.y;
        a = __half22float2(h0[2]); b = __half22float2(h1[2]);
        r1.x = a.x + b.x; r1.y = a.y + b.y;
        a = __half22float2(h0[3]); b = __half22float2(h1[3]);
        r1.z = a.x + b.x; r1.w = a.y + b.y;
    }
    ((float4*)out)[idx * 2]     = r0;
    ((float4*)out)[idx * 2 + 1] = r1;
}

// ---------------- launch -----------------------------------------------------
extern "C" void kernel_launch(void* const* d_in, const int* in_sizes, int n_in,
                              void* d_out, int out_size) {
    const float* x  = (const float*)d_in[0];  // [2,2048,1024]
    const float* gw = (const float*)d_in[1];  // [8,1024]
    const float* w1 = (const float*)d_in[2];  // [8,2048,1024]
    const float* w2 = (const float*)d_in[3];  // [8,1024,2048]
    const float* w3 = (const float*)d_in[4];  // [8,2048,1024]
    float* out = (float*)d_out;

    const size_t final_elems = (size_t)T_TOK * H_DIM;
    int write_logits = ((size_t)out_size >= final_elems + (size_t)T_TOK * NEXP) ? 1 : 0;
    float* logits = out + final_elems;

    const int dynsm = STAGES * 36864;   // 110592 per CTA -> 2 CTAs/SM
    cudaFuncSetAttribute(gemm1_tc, cudaFuncAttributeMaxDynamicSharedMemorySize, dynsm);
    cudaFuncSetAttribute(gemm2_tc, cudaFuncAttributeMaxDynamicSharedMemorySize, dynsm);

    // prolog: 16384 w1/w3-cvt blocks + 512 router blocks (8 tokens each)
    prolog_kernel<<<WBLK + T_TOK / 8, 256>>>(w1, w3, x, gw, logits, write_logits);

    // gemm1 tiles + appended w2-conversion blocks (flat 1D grid)
    gemm1_tc<<<G1T + W2BLK, 128, dynsm>>>(w2);

    dim3 g2(H_DIM / 128, T_TOK / 128, NEXP);   // (8, 32, 8)
    gemm2_tc<<<g2, 128, dynsm>>>(x);

    combine_kernel<<<(T_TOK * H_DIM / 8 + 255) / 256, 256>>>(out);
}

// round 15
// speedup vs baseline: 1.0083x; 1.0083x over previous
#include <cuda_runtime.h>
#include <cuda_fp16.h>
#include <math.h>
#include <stdint.h>

#define T_TOK 4096
#define H_DIM 1024
#define FF_DIM 2048
#define NEXP 8
#define SSH 72           // padded row stride in halves (144 B)
#define STAGES 3
#define WBLK 4096        // w1/w3-conversion blocks in prolog (4 float4/thr/array)
#define G1T  8192        // gemm1 GEMM tiles (32 ff x 32 row x 8 e)
#define W2BLK 8192       // w2-conversion blocks appended to gemm1 grid

// ---------------- device scratch (allocation-guard safe) --------------------
__device__ int      g_counts[NEXP];              // zero-init; combine re-zeros
__device__ int      g_tok[NEXP][T_TOK];          // packed: tok | slot<<16
__device__ float    g_wslot[2 * T_TOK];
__device__ __half   g_innerh[(size_t)NEXP * T_TOK * FF_DIM];  // 128 MB
__device__ float    g_comb[(size_t)2 * T_TOK * H_DIM];        // 32 MB
__device__ __half   g_w1h[(size_t)NEXP * FF_DIM * H_DIM];     // 32 MB
__device__ __half   g_w3h[(size_t)NEXP * FF_DIM * H_DIM];     // 32 MB
__device__ __half   g_w2h[(size_t)NEXP * H_DIM * FF_DIM];     // 32 MB
__device__ __half   g_xh[(size_t)T_TOK * H_DIM];              // 8 MB

// ---------------- helpers ----------------------------------------------------
__device__ __forceinline__ uint32_t h2u(float a, float b) {
    __half2 h = __floats2half2_rn(a, b);
    return *(uint32_t*)&h;
}
__device__ __forceinline__ uint2 cvt4h(float4 v) {
    uint2 u; u.x = h2u(v.x, v.y); u.y = h2u(v.z, v.w); return u;
}
__device__ __forceinline__ void mma16h(float* c, const uint32_t* a, const uint32_t* b) {
    asm volatile(
        "mma.sync.aligned.m16n8k16.row.col.f32.f16.f16.f32 "
        "{%0,%1,%2,%3}, {%4,%5,%6,%7}, {%8,%9}, {%0,%1,%2,%3};"
        : "+f"(c[0]), "+f"(c[1]), "+f"(c[2]), "+f"(c[3])
        : "r"(a[0]), "r"(a[1]), "r"(a[2]), "r"(a[3]), "r"(b[0]), "r"(b[1]));
}
#define LDSM4(r0, r1, r2, r3, addr) \
    asm volatile("ldmatrix.sync.aligned.m8n8.x4.shared.b16 {%0,%1,%2,%3}, [%4];" \
                 : "=r"(r0), "=r"(r1), "=r"(r2), "=r"(r3) : "r"(addr))
#define CP16(dst, src) \
    asm volatile("cp.async.cg.shared.global [%0], [%1], 16;" \
                 :: "r"(dst), "l"(src) : "memory")
#define CPCOMMIT() asm volatile("cp.async.commit_group;" ::: "memory")
#define CPWAIT1()  asm volatile("cp.async.wait_group 1;" ::: "memory")
#define CPWAIT0()  asm volatile("cp.async.wait_group 0;" ::: "memory")

// ---------------- prolog: w1/w3 cvt (blocks < WBLK) + router (rest) ---------
// Conversion blocks: each thread converts 4 float4s per array, strided by
// WBLK*256 elements (1 MB apart) -> 8 independent DRAM loads in flight.
// g_counts is re-zeroed by combine_kernel at the end of every invocation
// (and __device__ globals are zero-initialized), so the router always sees
// counts==0 with no intra-kernel race.
__global__ void prolog_kernel(const float* __restrict__ w1,
                              const float* __restrict__ w3,
                              const float* __restrict__ x,
                              const float* __restrict__ gw,
                              float* __restrict__ logits_out,
                              int write_logits) {
    if (blockIdx.x < WBLK) {
        size_t i = (size_t)blockIdx.x * 256 + threadIdx.x;
        const float4* s1 = (const float4*)w1;
        const float4* s3 = (const float4*)w3;
        float4 v1[4], v3[4];
#pragma unroll
        for (int j = 0; j < 4; j++) {
            size_t idx = i + (size_t)j * (WBLK * 256);
            v1[j] = s1[idx];
            v3[j] = s3[idx];
        }
#pragma unroll
        for (int j = 0; j < 4; j++) {
            size_t idx = i + (size_t)j * (WBLK * 256);
            ((uint2*)g_w1h)[idx] = cvt4h(v1[j]);
            ((uint2*)g_w3h)[idx] = cvt4h(v3[j]);
        }
        return;
    }

    int warp = (((int)blockIdx.x - WBLK) * blockDim.x + threadIdx.x) >> 5;
    int lane = threadIdx.x & 31;
    if (warp >= T_TOK) return;

    const float* xr = x + (size_t)warp * H_DIM;

    for (int i = lane; i < H_DIM / 2; i += 32) {
        float2 v = ((const float2*)xr)[i];
        ((uint32_t*)g_xh)[(size_t)warp * (H_DIM / 2) + i] = h2u(v.x, v.y);
    }

    float xv[32];
#pragma unroll
    for (int i = 0; i < 32; i++) xv[i] = xr[lane + 32 * i];

    float lg[NEXP];
#pragma unroll
    for (int e = 0; e < NEXP; e++) {
        const float* g = gw + (size_t)e * H_DIM;
        float s = 0.f;
#pragma unroll
        for (int i = 0; i < 32; i++) s += xv[i] * g[lane + 32 * i];
#pragma unroll
        for (int o = 16; o > 0; o >>= 1) s += __shfl_xor_sync(0xffffffffu, s, o);
        lg[e] = s;
    }

    if (lane == 0) {
        if (write_logits) {
#pragma unroll
            for (int e = 0; e < NEXP; e++)
                logits_out[(size_t)warp * NEXP + e] = lg[e];
        }
        float mx = lg[0];
#pragma unroll
        for (int e = 1; e < NEXP; e++) mx = fmaxf(mx, lg[e]);
        float p[NEXP], sum = 0.f;
#pragma unroll
        for (int e = 0; e < NEXP; e++) { p[e] = expf(lg[e] - mx); sum += p[e]; }
#pragma unroll
        for (int e = 0; e < NEXP; e++) p[e] /= sum;
        int i1 = 0;
#pragma unroll
        for (int e = 1; e < NEXP; e++) if (p[e] > p[i1]) i1 = e;
        int i2 = (i1 == 0) ? 1 : 0;
#pragma unroll
        for (int e = 0; e < NEXP; e++) if (e != i1 && p[e] > p[i2]) i2 = e;
        float s2 = p[i1] + p[i2];
        int pos = atomicAdd(&g_counts[i1], 1);
        g_tok[i1][pos] = warp;                 // slot 0
        pos = atomicAdd(&g_counts[i2], 1);
        g_tok[i2][pos] = warp | 0x10000;       // slot 1
        g_wslot[warp]         = p[i1] / s2;
        g_wslot[T_TOK + warp] = p[i2] / s2;
    }
}

// ---------------- GEMM1 (+ appended w2 conversion blocks) -------------------
// GEMM: block 128M x 32N-dual(64 eff) x 64K; 4 warps = 2M x 2N; warp tile
// 64x32 per matrix; 128 threads, 2 CTAs/SM, 3-stage cp.async ring (frozen).
#define G1_SZ   36864u           // (128+64+64)*144
#define G1_B1O  18432u           // 128*144
#define G1_B3O  27648u           // 192*144

__global__ void __launch_bounds__(128, 2)
gemm1_tc(const float* __restrict__ w2src) {
    extern __shared__ __align__(16) char smc[];
    const uint32_t sbase = (uint32_t)__cvta_generic_to_shared(smc);

    if (blockIdx.x >= G1T) {
        // w2 conversion: 8192 blocks x 128 thr x 4 float4
        size_t i = (size_t)(blockIdx.x - G1T) * 128 + threadIdx.x;
        const float4* src = (const float4*)w2src;
#pragma unroll
        for (int j = 0; j < 4; j++) {
            size_t idx = i + (size_t)j * (W2BLK * 128);
            ((uint2*)g_w2h)[idx] = cvt4h(src[idx]);
        }
        return;
    }

    const int f = blockIdx.x;
    const int e = f >> 10;              // 1024 tiles per expert
    const int row0 = ((f >> 5) & 31) * 128;
    const int ff0 = (f & 31) * 64;
    const int n = g_counts[e];
    if (row0 >= n) return;

    const int tid = threadIdx.x;
    const int wid = tid >> 5, lane = tid & 31;
    const int wm = wid & 1, wn = wid >> 1;        // 2M x 2N
    const int g = lane >> 2, t = lane & 3;

    const __half* apt[8];
#pragma unroll
    for (int i = 0; i < 8; i++) {
        int r = row0 + (tid >> 3) + 16 * i;
        int tok = (r < n) ? (g_tok[e][r] & 0xFFFF) : 0;
        apt[i] = g_xh + (size_t)tok * H_DIM + (tid & 7) * 8;
    }
    const __half* b1p0 = g_w1h + ((size_t)e * FF_DIM + ff0 + (tid >> 3)) * H_DIM + (tid & 7) * 8;
    const __half* b3p0 = g_w3h + ((size_t)e * FF_DIM + ff0 + (tid >> 3)) * H_DIM + (tid & 7) * 8;
    const uint32_t off0 = (uint32_t)((tid >> 3) * SSH + (tid & 7) * 8) * 2u;
    const uint32_t ostep = 16u * SSH * 2u;

    auto issue = [&](int s) {
        uint32_t base = sbase + (uint32_t)(s % STAGES) * G1_SZ;
        int k0 = s * 64;
        uint32_t o = off0;
#pragma unroll
        for (int i = 0; i < 8; i++) { CP16(base + o, apt[i] + k0); o += ostep; }
        o = off0;
#pragma unroll
        for (int i = 0; i < 4; i++) {
            CP16(base + G1_B1O + o, b1p0 + (size_t)16 * i * H_DIM + k0);
            CP16(base + G1_B3O + o, b3p0 + (size_t)16 * i * H_DIM + k0);
            o += ostep;
        }
        CPCOMMIT();
    };

    float acc1[4][4][4], acc3[4][4][4];
#pragma unroll
    for (int mb = 0; mb < 4; mb++)
#pragma unroll
        for (int nb = 0; nb < 4; nb++)
#pragma unroll
            for (int j = 0; j < 4; j++) { acc1[mb][nb][j] = 0.f; acc3[mb][nb][j] = 0.f; }

    uint32_t aLb0 = (uint32_t)((wm * 64 + (lane & 15)) * SSH) * 2u
                  + (uint32_t)(lane >> 4) * 16u;
    const uint32_t aMstep = 16u * SSH * 2u;
    uint32_t bLb[2];
#pragma unroll
    for (int p = 0; p < 2; p++)
        bLb[p] = (uint32_t)((wn * 32 + p * 16 + ((lane >> 4) << 3) + (lane & 7)) * SSH) * 2u
               + (uint32_t)((lane >> 3) & 1) * 16u;

    issue(0); issue(1);

    const int NIT = H_DIM / 64;     // 16
    for (int it = 0; it < NIT; ++it) {
        if (it + 1 < NIT) CPWAIT1(); else CPWAIT0();
        __syncthreads();
        if (it + STAGES - 1 < NIT) issue(it + STAGES - 1);

        const uint32_t sb  = sbase + (uint32_t)(it % STAGES) * G1_SZ;
        const uint32_t b1b = sb + G1_B1O;
        const uint32_t b3b = sb + G1_B3O;

#pragma unroll
        for (int kk = 0; kk < 4; kk++) {
            const uint32_t ko = (uint32_t)kk * 32u;
            uint32_t a[4][4], b1[4][2], b3[4][2];
#pragma unroll
            for (int mb = 0; mb < 4; mb++)
                LDSM4(a[mb][0], a[mb][1], a[mb][2], a[mb][3],
                      sb + aLb0 + (uint32_t)mb * aMstep + ko);
#pragma unroll
            for (int p = 0; p < 2; p++) {
                LDSM4(b1[2*p][0], b1[2*p][1], b1[2*p+1][0], b1[2*p+1][1], b1b + bLb[p] + ko);
                LDSM4(b3[2*p][0], b3[2*p][1], b3[2*p+1][0], b3[2*p+1][1], b3b + bLb[p] + ko);
            }
#pragma unroll
            for (int mb = 0; mb < 4; mb++)
#pragma unroll
                for (int nb = 0; nb < 4; nb++) {
                    mma16h(acc1[mb][nb], a[mb], b1[nb]);
                    mma16h(acc3[mb][nb], a[mb], b3[nb]);
                }
        }
    }

    // fused SwiGLU epilogue -> g_innerh
#pragma unroll
    for (int mb = 0; mb < 4; mb++) {
        int r0 = row0 + wm * 64 + mb * 16 + g;
        int r1 = r0 + 8;
#pragma unroll
        for (int nb = 0; nb < 4; nb++) {
            int col = ff0 + wn * 32 + nb * 8 + 2 * t;
            if (r0 < n) {
                float a0 = acc1[mb][nb][0], a1 = acc1[mb][nb][1];
                float v0 = (a0 / (1.f + expf(-a0))) * acc3[mb][nb][0];
                float v1 = (a1 / (1.f + expf(-a1))) * acc3[mb][nb][1];
                *(uint32_t*)&g_innerh[((size_t)e * T_TOK + r0) * FF_DIM + col] = h2u(v0, v1);
            }
            if (r1 < n) {
                float a2 = acc1[mb][nb][2], a3 = acc1[mb][nb][3];
                float v2 = (a2 / (1.f + expf(-a2))) * acc3[mb][nb][2];
                float v3 = (a3 / (1.f + expf(-a3))) * acc3[mb][nb][3];
                *(uint32_t*)&g_innerh[((size_t)e * T_TOK + r1) * FF_DIM + col] = h2u(v2, v3);
            }
        }
    }
}

// ---------------- GEMM2: comb[slot][tok] = inner @ W2^T, fp16 MMA -----------
// block 128M x 128N x 64K; 4 warps = 2M x 2N; warp tile 64x64.
// 128 threads, 2 CTAs/SM, 3-stage cp.async ring. (round-11, frozen)
#define G2_SZ  36864u            // (128+128)*144
#define G2_BO  18432u            // 128*144

__global__ void __launch_bounds__(128, 2)
gemm2_tc(const float* __restrict__ dummy) {
    extern __shared__ __align__(16) char smc[];
    const uint32_t sbase = (uint32_t)__cvta_generic_to_shared(smc);

    const int e = blockIdx.z;
    const int n = g_counts[e];
    const int row0 = blockIdx.y * 128;
    if (row0 >= n) return;
    const int h0 = blockIdx.x * 128;

    const int tid = threadIdx.x;
    const int wid = tid >> 5, lane = tid & 31;
    const int wm = wid & 1, wn = wid >> 1;        // 2M x 2N
    const int g = lane >> 2, t = lane & 3;

    const __half* ap0 = g_innerh + ((size_t)e * T_TOK + row0 + (tid >> 3)) * FF_DIM + (tid & 7) * 8;
    const __half* bp0 = g_w2h + ((size_t)e * H_DIM + h0 + (tid >> 3)) * FF_DIM + (tid & 7) * 8;
    const uint32_t off0 = (uint32_t)((tid >> 3) * SSH + (tid & 7) * 8) * 2u;
    const uint32_t ostep = 16u * SSH * 2u;
    const size_t pstep = (size_t)16 * FF_DIM;

    auto issue = [&](int s) {
        uint32_t base = sbase + (uint32_t)(s % STAGES) * G2_SZ;
        int k0 = s * 64;
        const __half* ap = ap0 + k0;
        const __half* bp = bp0 + k0;
        uint32_t o = off0;
#pragma unroll
        for (int i = 0; i < 8; i++) {
            CP16(base + o, ap);
            CP16(base + G2_BO + o, bp);
            ap += pstep; bp += pstep; o += ostep;
        }
        CPCOMMIT();
    };

    float acc[4][8][4];
#pragma unroll
    for (int mb = 0; mb < 4; mb++)
#pragma unroll
        for (int nb = 0; nb < 8; nb++)
#pragma unroll
            for (int j = 0; j < 4; j++) acc[mb][nb][j] = 0.f;

    uint32_t aLb0 = (uint32_t)((wm * 64 + (lane & 15)) * SSH) * 2u
                  + (uint32_t)(lane >> 4) * 16u;
    const uint32_t aMstep = 16u * SSH * 2u;
    uint32_t bLb[4];
#pragma unroll
    for (int p = 0; p < 4; p++)
        bLb[p] = (uint32_t)((wn * 64 + p * 16 + ((lane >> 4) << 3) + (lane & 7)) * SSH) * 2u
               + (uint32_t)((lane >> 3) & 1) * 16u;

    issue(0); issue(1);

    const int NIT = FF_DIM / 64;    // 32
    for (int it = 0; it < NIT; ++it) {
        if (it + 1 < NIT) CPWAIT1(); else CPWAIT0();
        __syncthreads();
        if (it + STAGES - 1 < NIT) issue(it + STAGES - 1);

        const uint32_t sb = sbase + (uint32_t)(it % STAGES) * G2_SZ;
        const uint32_t bb = sb + G2_BO;

#pragma unroll
        for (int kk = 0; kk < 4; kk++) {
            const uint32_t ko = (uint32_t)kk * 32u;
            uint32_t a[4][4], b[8][2];
#pragma unroll
            for (int mb = 0; mb < 4; mb++)
                LDSM4(a[mb][0], a[mb][1], a[mb][2], a[mb][3],
                      sb + aLb0 + (uint32_t)mb * aMstep + ko);
#pragma unroll
            for (int p = 0; p < 4; p++)
                LDSM4(b[2*p][0], b[2*p][1], b[2*p+1][0], b[2*p+1][1], bb + bLb[p] + ko);
#pragma unroll
            for (int mb = 0; mb < 4; mb++)
#pragma unroll
                for (int nb = 0; nb < 8; nb++)
                    mma16h(acc[mb][nb], a[mb], b[nb]);
        }
    }

    // non-atomic scatter into per-slot combine buffers
#pragma unroll
    for (int mb = 0; mb < 4; mb++) {
        int r0 = row0 + wm * 64 + mb * 16 + g;
        int r1 = r0 + 8;
        int pk0 = (r0 < n) ? g_tok[e][r0] : -1;
        int pk1 = (r1 < n) ? g_tok[e][r1] : -1;
        float* d0 = (pk0 >= 0)
            ? &g_comb[((size_t)(pk0 >> 16) * T_TOK + (pk0 & 0xFFFF)) * H_DIM] : 0;
        float* d1 = (pk1 >= 0)
            ? &g_comb[((size_t)(pk1 >> 16) * T_TOK + (pk1 & 0xFFFF)) * H_DIM] : 0;
#pragma unroll
        for (int nb = 0; nb < 8; nb++) {
            int col = h0 + wn * 64 + nb * 8 + 2 * t;
            if (d0) { float2 v; v.x = acc[mb][nb][0]; v.y = acc[mb][nb][1];
                      *(float2*)&d0[col] = v; }
            if (d1) { float2 v; v.x = acc[mb][nb][2]; v.y = acc[mb][nb][3];
                      *(float2*)&d1[col] = v; }
        }
    }
}

// ---------------- combine: out = w0*comb0 + w1*comb1; re-zero counts --------
__global__ void combine_kernel(float* __restrict__ out) {
    int idx = blockIdx.x * blockDim.x + threadIdx.x;
    const int nq = T_TOK * H_DIM / 4;
    if (blockIdx.x == 0 && threadIdx.x < NEXP)
        g_counts[threadIdx.x] = 0;           // reset for the NEXT invocation
    if (idx >= nq) return;
    int tk = idx / (H_DIM / 4);
    float w0 = g_wslot[tk], w1 = g_wslot[T_TOK + tk];
    float4 v0 = ((const float4*)g_comb)[idx];
    float4 v1 = ((const float4*)g_comb)[(size_t)(T_TOK * H_DIM / 4) + idx];
    float4 r;
    r.x = w0 * v0.x + w1 * v1.x;
    r.y = w0 * v0.y + w1 * v1.y;
    r.z = w0 * v0.z + w1 * v1.z;
    r.w = w0 * v0.w + w1 * v1.w;
    ((float4*)out)[idx] = r;
}

// ---------------- launch -----------------------------------------------------
extern "C" void kernel_launch(void* const* d_in, const int* in_sizes, int n_in,
                              void* d_out, int out_size) {
    const float* x  = (const float*)d_in[0];  // [2,2048,1024]
    const float* gw = (const float*)d_in[1];  // [8,1024]
    const float* w1 = (const float*)d_in[2];  // [8,2048,1024]
    const float* w2 = (const float*)d_in[3];  // [8,1024,2048]
    const float* w3 = (const float*)d_in[4];  // [8,2048,1024]
    float* out = (float*)d_out;

    const size_t final_elems = (size_t)T_TOK * H_DIM;
    int write_logits = ((size_t)out_size >= final_elems + (size_t)T_TOK * NEXP) ? 1 : 0;
    float* logits = out + final_elems;

    const int dynsm = STAGES * 36864;   // 110592 per CTA -> 2 CTAs/SM
    cudaFuncSetAttribute(gemm1_tc, cudaFuncAttributeMaxDynamicSharedMemorySize, dynsm);
    cudaFuncSetAttribute(gemm2_tc, cudaFuncAttributeMaxDynamicSharedMemorySize, dynsm);

    // prolog: 4096 w1/w3-cvt blocks (4 float4/thr/array) + 512 router blocks
    prolog_kernel<<<WBLK + T_TOK / 8, 256>>>(w1, w3, x, gw, logits, write_logits);

    // gemm1 tiles + appended w2-conversion blocks (flat 1D grid)
    gemm1_tc<<<G1T + W2BLK, 128, dynsm>>>(w2);

    dim3 g2(H_DIM / 128, T_TOK / 128, NEXP);   // (8, 32, 8)
    gemm2_tc<<<g2, 128, dynsm>>>(x);

    combine_kernel<<<(T_TOK * H_DIM / 4 + 255) / 256, 256>>>(out);
}